// round 16
// baseline (speedup 1.0000x reference)
#include <cuda_runtime.h>
#include <cuda_bf16.h>
#include <cuda_fp16.h>
#include <cfloat>
#include <cstddef>
#include <cstdint>

// Problem constants (fixed by the reference)
#define Bn 16
#define Tn 2048
#define Dn 256
#define Qn 4
#define Kn 1024
#define Mn (Bn*Tn)          // 32768 tokens

#define LOSS_SLOTS 1024
#define WWIN  4.0f           // certainty margin / candidate window (> 2E + pack eps)
#define GGUARD 0.1f          // pack-perturbation guard for candidate test
#define CANDG 16             // max candidate groups (8 codes each)

// ------------------------- device global scratch ---------------------------
__device__ __align__(16) float          g_residual[Mn*Dn];
__device__ __align__(16) float          g_c2[Qn*Kn];
__device__ __align__(16) float          g_r2[Mn];
__device__              double          g_losspart[LOSS_SLOTS];
__device__ __align__(16) __nv_bfloat16  g_Apack[(size_t)Mn*Dn];      // bf16(residual)
__device__ __align__(16) __nv_bfloat16  g_Bpack[(size_t)Qn*Kn*Dn];   // bf16(codebooks)
__device__ __align__(16) float2         g_g2[(size_t)Mn*128];        // per-8-code-group (v1|idx, v2)

// ------------------------------ PTX helpers --------------------------------
__device__ __forceinline__ uint32_t smem_to_u32(const void* p) {
    uint32_t a;
    asm("{ .reg .u64 t; cvta.to.shared.u64 t, %1; cvt.u32.u64 %0, t; }"
        : "=r"(a) : "l"(p));
    return a;
}
#define CP_ASYNC16(dst, src) \
    asm volatile("cp.async.cg.shared.global [%0], [%1], 16;" :: "r"(dst), "l"(src))
#define CP_COMMIT() asm volatile("cp.async.commit_group;" ::: "memory")
#define CP_WAIT0()  asm volatile("cp.async.wait_group 0;" ::: "memory")
#define LDSM_X4(r0, r1, r2, r3, addr) \
    asm volatile("ldmatrix.sync.aligned.m8n8.x4.shared.b16 {%0,%1,%2,%3}, [%4];" \
                 : "=r"(r0), "=r"(r1), "=r"(r2), "=r"(r3) : "r"(addr))
#define MMA16816(c, a, b0v, b1v) \
    asm volatile("mma.sync.aligned.m16n8k16.row.col.f32.bf16.bf16.f32 " \
                 "{%0,%1,%2,%3}, {%4,%5,%6,%7}, {%8,%9}, {%0,%1,%2,%3};" \
                 : "+f"((c)[0]), "+f"((c)[1]), "+f"((c)[2]), "+f"((c)[3]) \
                 : "r"((a)[0]), "r"((a)[1]), "r"((a)[2]), "r"((a)[3]), \
                   "r"(b0v), "r"(b1v))

// top-2 merge over packed-score pairs (idx lives in v1 low bits; positive
// scores => packed floats give automatic lowest-index-on-tie ordering).
__device__ __forceinline__ void top2p_merge(float& v1, float& v2, float b1, float b2) {
    if (b1 < v1) { v2 = fminf(v1, b2); v1 = b1; }
    else         { v2 = fminf(v2, b1); }
}

// ---------------------------------------------------------------------------
// prep0: residual = x, bf16 pack, r2 (XLA-exact order), zero loss slots.
// ---------------------------------------------------------------------------
__global__ void prep0_kernel(const float* __restrict__ x) {
    int wid = threadIdx.x >> 5, lane = threadIdx.x & 31;
    int token = blockIdx.x * 8 + wid;
    size_t base = (size_t)token * Dn;
    float s = 0.f;
    #pragma unroll
    for (int j = 0; j < 8; j++) {
        int d = lane + 32 * j;
        float v = x[base + d];
        g_residual[base + d] = v;
        g_Apack[base + d] = __float2bfloat16_rn(v);
        s = __fadd_rn(s, __fmul_rn(v, v));
    }
    #pragma unroll
    for (int off = 16; off; off >>= 1)
        s = __fadd_rn(s, __shfl_down_sync(0xffffffffu, s, off));
    if (lane == 0) g_r2[token] = s;
    if (blockIdx.x == 0) {
        for (int i = threadIdx.x; i < LOSS_SLOTS; i += 256) g_losspart[i] = 0.0;
    }
}

// codebooks -> bf16 pack + c2 (XLA-exact order), one warp per codeword
__global__ void packBc2_kernel(const float* __restrict__ cbs) {
    int w    = (blockIdx.x * blockDim.x + threadIdx.x) >> 5;
    int lane = threadIdx.x & 31;
    if (w >= Qn * Kn) return;
    const float* row = cbs + (size_t)w * Dn;
    float s = 0.f;
    #pragma unroll
    for (int j = 0; j < 8; j++) {
        int d = lane + 32 * j;
        float v = row[d];
        g_Bpack[(size_t)w * Dn + d] = __float2bfloat16_rn(v);
        s = __fadd_rn(s, __fmul_rn(v, v));
    }
    #pragma unroll
    for (int off = 16; off; off >>= 1)
        s = __fadd_rn(s, __shfl_down_sync(0xffffffffu, s, off));
    if (lane == 0) g_c2[w] = s;
}

// ---------------------------------------------------------------------------
// bf16 HMMA GEMM: 128 tokens/CTA x 1024 codes, K=256. A resident in SMEM,
// B double-buffered, 128 threads (4 warps, 2x2), warp tile 64x64, register
// double-buffered fragments (round-15 mainloop, unchanged numerics).
// Epilogue: per-8-code-group top-2 with group-argmin index packed into v1's
// low 10 mantissa bits -> g_g2. No score / hmin arrays.
// ---------------------------------------------------------------------------
#define SM_A  0                      // 4 chunks x 16384 = 65536
#define SM_B0 65536
#define SM_B1 (65536 + 16384)
#define SM_C2 (65536 + 32768)
#define SM_TOT (65536 + 32768 + 4096)

__global__ void __launch_bounds__(128, 2)
gemm_kernel(int q)
{
    extern __shared__ char smem[];
    uint32_t sb = smem_to_u32(smem);
    float* c2s = (float*)(smem + SM_C2);

    int tid = threadIdx.x, lane = tid & 31, wid = tid >> 5;
    int wm = wid >> 1, wn = wid & 1;           // 2 x 2 warp grid, tile 64x64
    int rowBase = blockIdx.x * 128;

    for (int i = tid; i < Kn; i += 128) c2s[i] = g_c2[q * Kn + i];

    float r2a[4][2];
    #pragma unroll
    for (int mf = 0; mf < 4; mf++)
        #pragma unroll
        for (int h = 0; h < 2; h++)
            r2a[mf][h] = g_r2[rowBase + wm * 64 + mf * 16 + (lane >> 2) + h * 8];

    const __nv_bfloat16* baseB = g_Bpack + (size_t)q * Kn * Dn;

    // A -> SMEM once: chunked layout [cc][row][64k]; 32 x 16B per thread
    #pragma unroll
    for (int j = 0; j < 32; j++) {
        int linear = tid + 128 * j;
        int row = linear >> 5;
        int m8  = linear & 31;
        int cc  = m8 >> 3, m8c = m8 & 7;
        uint32_t sw = (uint32_t)((m8c ^ (row & 7)) << 4);
        CP_ASYNC16(sb + SM_A + cc * 16384 + row * 128 + sw,
                   g_Apack + (size_t)(rowBase + row) * Dn + m8 * 8);
    }
    CP_COMMIT();

    // B chunk 0
    #pragma unroll
    for (int j = 0; j < 8; j++) {
        int linear = tid + 128 * j;
        int row = linear >> 3, m8 = linear & 7;
        uint32_t sw = (uint32_t)((m8 ^ (row & 7)) << 4);
        CP_ASYNC16(sb + SM_B0 + row * 128 + sw,
                   baseB + (size_t)row * Dn + m8 * 8);
    }
    CP_COMMIT();

    float acc[4][8][4];
    #pragma unroll
    for (int a = 0; a < 4; a++)
        #pragma unroll
        for (int b = 0; b < 8; b++)
            #pragma unroll
            for (int c = 0; c < 4; c++) acc[a][b][c] = 0.f;

    const int tq = lane >> 3;

    for (int bc = 0; bc < 32; bc++) {
        int nt = bc >> 2, cc = bc & 3;
        CP_WAIT0();
        __syncthreads();

        if (bc < 31) {
            int nbc = bc + 1;
            int nnt = nbc >> 2, ncc = nbc & 3;
            uint32_t buf = (nbc & 1) ? SM_B1 : SM_B0;
            int koff = ncc * 64;
            #pragma unroll
            for (int j = 0; j < 8; j++) {
                int linear = tid + 128 * j;
                int row = linear >> 3, m8 = linear & 7;
                uint32_t sw = (uint32_t)((m8 ^ (row & 7)) << 4);
                CP_ASYNC16(sb + buf + row * 128 + sw,
                           baseB + (size_t)(nnt * 128 + row) * Dn + koff + m8 * 8);
            }
            CP_COMMIT();
        }

        uint32_t abase = sb + SM_A + cc * 16384;
        uint32_t bbase = sb + ((bc & 1) ? SM_B1 : SM_B0);

        uint32_t afr[2][4][4], bfr[2][4][4];

        #pragma unroll
        for (int mf = 0; mf < 4; mf++) {
            int row = wm * 64 + mf * 16 + (lane & 7) + ((tq & 1) << 3);
            int kk  = (tq >> 1) << 3;
            uint32_t addr = abase + row * 128 + ((((kk >> 3) ^ (row & 7)) << 4));
            LDSM_X4(afr[0][mf][0], afr[0][mf][1], afr[0][mf][2], afr[0][mf][3], addr);
        }
        #pragma unroll
        for (int nf2 = 0; nf2 < 4; nf2++) {
            int row = wn * 64 + nf2 * 16 + ((tq >> 1) << 3) + (lane & 7);
            int kk  = (tq & 1) << 3;
            uint32_t addr = bbase + row * 128 + ((((kk >> 3) ^ (row & 7)) << 4));
            LDSM_X4(bfr[0][nf2][0], bfr[0][nf2][1], bfr[0][nf2][2], bfr[0][nf2][3], addr);
        }

        #pragma unroll
        for (int ks = 0; ks < 4; ks++) {
            int cur = ks & 1, nxt = cur ^ 1;
            if (ks < 3) {
                #pragma unroll
                for (int mf = 0; mf < 4; mf++) {
                    int row = wm * 64 + mf * 16 + (lane & 7) + ((tq & 1) << 3);
                    int kk  = (ks + 1) * 16 + ((tq >> 1) << 3);
                    uint32_t addr = abase + row * 128 + ((((kk >> 3) ^ (row & 7)) << 4));
                    LDSM_X4(afr[nxt][mf][0], afr[nxt][mf][1], afr[nxt][mf][2], afr[nxt][mf][3], addr);
                }
                #pragma unroll
                for (int nf2 = 0; nf2 < 4; nf2++) {
                    int row = wn * 64 + nf2 * 16 + ((tq >> 1) << 3) + (lane & 7);
                    int kk  = (ks + 1) * 16 + ((tq & 1) << 3);
                    uint32_t addr = bbase + row * 128 + ((((kk >> 3) ^ (row & 7)) << 4));
                    LDSM_X4(bfr[nxt][nf2][0], bfr[nxt][nf2][1], bfr[nxt][nf2][2], bfr[nxt][nf2][3], addr);
                }
            }
            #pragma unroll
            for (int nf2 = 0; nf2 < 4; nf2++) {
                #pragma unroll
                for (int mf = 0; mf < 4; mf++) {
                    MMA16816(acc[mf][nf2 * 2],     afr[cur][mf], bfr[cur][nf2][0], bfr[cur][nf2][1]);
                    MMA16816(acc[mf][nf2 * 2 + 1], afr[cur][mf], bfr[cur][nf2][2], bfr[cur][nf2][3]);
                }
            }
        }

        if (cc == 3) {
            // ---- epilogue tile nt: per-8-code-group top-2 (+packed idx) ----
            #pragma unroll
            for (int mf = 0; mf < 4; mf++) {
                int ra = rowBase + wm * 64 + mf * 16 + (lane >> 2);
                #pragma unroll
                for (int nf = 0; nf < 8; nf++) {
                    int col = nt * 128 + wn * 64 + nf * 8 + (lane & 3) * 2;
                    float cA = c2s[col], cB = c2s[col + 1];
                    float s0x = __fadd_rn(__fsub_rn(r2a[mf][0], __fmul_rn(2.f, acc[mf][nf][0])), cA);
                    float s0y = __fadd_rn(__fsub_rn(r2a[mf][0], __fmul_rn(2.f, acc[mf][nf][1])), cB);
                    float s1x = __fadd_rn(__fsub_rn(r2a[mf][1], __fmul_rn(2.f, acc[mf][nf][2])), cA);
                    float s1y = __fadd_rn(__fsub_rn(r2a[mf][1], __fmul_rn(2.f, acc[mf][nf][3])), cB);

                    // in-lane top-2 per row (lower col wins on tie)
                    float a1 = s0x, a2 = s0y; int ai = col;
                    if (s0y < s0x) { a1 = s0y; a2 = s0x; ai = col + 1; }
                    float b1 = s1x, b2 = s1y; int bi = col;
                    if (s1y < s1x) { b1 = s1y; b2 = s1x; bi = col + 1; }

                    // quad merge (4 lanes of a group) with idx tie-break
                    #pragma unroll
                    for (int off = 1; off <= 2; off <<= 1) {
                        float o1 = __shfl_xor_sync(0xffffffffu, a1, off);
                        float o2 = __shfl_xor_sync(0xffffffffu, a2, off);
                        int   oi = __shfl_xor_sync(0xffffffffu, ai, off);
                        if (o1 < a1 || (o1 == a1 && oi < ai)) { a2 = fminf(a1, o2); a1 = o1; ai = oi; }
                        else a2 = fminf(a2, o1);
                        o1 = __shfl_xor_sync(0xffffffffu, b1, off);
                        o2 = __shfl_xor_sync(0xffffffffu, b2, off);
                        oi = __shfl_xor_sync(0xffffffffu, bi, off);
                        if (o1 < b1 || (o1 == b1 && oi < bi)) { b2 = fminf(b1, o2); b1 = o1; bi = oi; }
                        else b2 = fminf(b2, o1);
                    }
                    if ((lane & 3) == 0) {
                        int g = nt * 16 + wn * 8 + nf;
                        uint32_t pa = (__float_as_uint(a1) & ~1023u) | (uint32_t)(ai & 1023);
                        uint32_t pb = (__float_as_uint(b1) & ~1023u) | (uint32_t)(bi & 1023);
                        g_g2[(size_t)ra * 128 + g]       = make_float2(__uint_as_float(pa), a2);
                        g_g2[(size_t)(ra + 8) * 128 + g] = make_float2(__uint_as_float(pb), b2);
                    }
                }
            }
            #pragma unroll
            for (int a = 0; a < 4; a++)
                #pragma unroll
                for (int b = 0; b < 8; b++)
                    #pragma unroll
                    for (int c = 0; c < 4; c++) acc[a][b][c] = 0.f;
        }
    }
}

// ---------------------------------------------------------------------------
// Fused scan + update. Reads 128 group-(v1|idx, v2) pairs (1 KB/token).
// Fast path: global margin >= WWIN -> winner = packed idx, nothing else read.
// Slow path: exact-evaluate all 8 codes of each candidate group with the
// round-3 bit-exact chain, lowest-index tie-break.
// ---------------------------------------------------------------------------
__global__ void scan_update_kernel(const float* __restrict__ cbs, int q,
                                   const float* __restrict__ x,
                                   float* __restrict__ out_idx_f,
                                   float* __restrict__ out_quant, int is_last)
{
    int wid = threadIdx.x >> 5, lane = threadIdx.x & 31;
    int token = blockIdx.x * 8 + wid;
    const float* cb = cbs + (size_t)q * Kn * Dn;
    size_t base = (size_t)token * Dn;

    // preload my 8 residual values (independent of winner; overlaps scan)
    float rres[8];
    #pragma unroll
    for (int j = 0; j < 8; j++) rres[j] = g_residual[base + lane + 32 * j];

    // 4 groups per lane (coalesced 2 x float4 = 32B)
    const float4* gp = (const float4*)(g_g2 + (size_t)token * 128);
    float4 ga = gp[lane * 2], gb = gp[lane * 2 + 1];

    float v1 = ga.x, v2 = ga.y;
    top2p_merge(v1, v2, ga.z, ga.w);
    top2p_merge(v1, v2, gb.x, gb.y);
    top2p_merge(v1, v2, gb.z, gb.w);
    #pragma unroll
    for (int off = 16; off; off >>= 1) {
        float o1 = __shfl_xor_sync(0xffffffffu, v1, off);
        float o2 = __shfl_xor_sync(0xffffffffu, v2, off);
        top2p_merge(v1, v2, o1, o2);
    }

    int winner;
    if (v2 - v1 >= WWIN) {
        winner = (int)(__float_as_uint(v1) & 1023u);   // certain winner
    } else {
        // ---- slow path: candidate groups, exact-evaluate 8 codes each ----
        __shared__ int cnts[8];
        __shared__ int lists[8][CANDG];
        if (lane == 0) cnts[wid] = 0;
        __syncwarp();
        float thr = v1 + WWIN + GGUARD;
        float mv[4] = {ga.x, ga.z, gb.x, gb.z};
        #pragma unroll
        for (int c = 0; c < 4; c++) {
            if (mv[c] <= thr) {
                int p = atomicAdd(&cnts[wid], 1);
                if (p < CANDG) lists[wid][p] = lane * 4 + c;
            }
        }
        __syncwarp();
        int cnt = cnts[wid];

        const float* rrow = g_residual + base;
        float r2 = g_r2[token];
        float bv = FLT_MAX; int bi = 0x7fffffff;
        if (cnt <= CANDG) {
            // lanes: j = lane>>3 selects group slot, lane&7 selects code
            for (int p = 0; p + (lane >> 3) < cnt; p += 4) {
                int g = lists[wid][p + (lane >> 3)];
                int k = g * 8 + (lane & 7);
                const float* cr = cb + (size_t)k * Dn;
                float acc = 0.f;
                #pragma unroll 8
                for (int d = 0; d < Dn; d++) acc = __fmaf_rn(rrow[d], cr[d], acc);
                float s = __fadd_rn(__fsub_rn(r2, __fmul_rn(2.f, acc)), g_c2[q * Kn + k]);
                if (s < bv || (s == bv && k < bi)) { bv = s; bi = k; }
            }
        } else {
            for (int k = lane; k < Kn; k += 32) {
                const float* cr = cb + (size_t)k * Dn;
                float acc = 0.f;
                #pragma unroll 8
                for (int d = 0; d < Dn; d++) acc = __fmaf_rn(rrow[d], cr[d], acc);
                float s = __fadd_rn(__fsub_rn(r2, __fmul_rn(2.f, acc)), g_c2[q * Kn + k]);
                if (s < bv || (s == bv && k < bi)) { bv = s; bi = k; }
            }
        }
        #pragma unroll
        for (int off = 16; off; off >>= 1) {
            float ov = __shfl_xor_sync(0xffffffffu, bv, off);
            int   oi = __shfl_xor_sync(0xffffffffu, bi, off);
            if (ov < bv || (ov == bv && oi < bi)) { bv = ov; bi = oi; }
        }
        winner = bi;
    }

    // ---- update (bit-exact residual chain; r2 in XLA-exact order) ----
    const float* cbrow = cb + (size_t)winner * Dn;
    float s = 0.f;
    #pragma unroll
    for (int j = 0; j < 8; j++) {
        int d = lane + 32 * j;
        float qv = cbrow[d];
        float r  = __fsub_rn(rres[j], qv);
        if (!is_last) {
            g_residual[base + d] = r;
            g_Apack[base + d] = __float2bfloat16_rn(r);
        } else {
            out_quant[base + d] = __fsub_rn(x[base + d], r);
        }
        s = __fadd_rn(s, __fmul_rn(r, r));
    }
    #pragma unroll
    for (int off = 16; off; off >>= 1)
        s = __fadd_rn(s, __shfl_down_sync(0xffffffffu, s, off));
    if (lane == 0) {
        if (!is_last) g_r2[token] = s;
        atomicAdd(&g_losspart[token & (LOSS_SLOTS - 1)], (double)s);
        out_idx_f[(size_t)q * Mn + token] = (float)winner;
    }
}

__global__ void finalize_kernel(float* __restrict__ out_loss)
{
    __shared__ double red[256];
    double s = 0.0;
    for (int i = threadIdx.x; i < LOSS_SLOTS; i += 256) s += g_losspart[i];
    red[threadIdx.x] = s;
    __syncthreads();
    #pragma unroll
    for (int st = 128; st > 0; st >>= 1) {
        if (threadIdx.x < st) red[threadIdx.x] += red[threadIdx.x + st];
        __syncthreads();
    }
    if (threadIdx.x == 0) {
        float v = (float)(1.25 * red[0] / (double)((size_t)Mn * Dn));
        #pragma unroll
        for (int q = 0; q < Qn; q++) out_loss[q] = v;
    }
}

// ---------------------------------------------------------------------------
extern "C" void kernel_launch(void* const* d_in, const int* in_sizes, int n_in,
                              void* d_out, int out_size)
{
    const float* x   = (const float*)d_in[0];
    const float* cbs = (const float*)d_in[1];
    if (n_in >= 2 && in_sizes[0] == Qn * Kn * Dn && in_sizes[1] == Mn * Dn) {
        const float* t = x; x = cbs; cbs = t;
    }

    float* out       = (float*)d_out;
    float* out_quant = out;                                       // [B,T,D]
    float* out_idx   = out + (size_t)Mn * Dn;                     // [Q,B,T]
    float* out_loss  = out + (size_t)Mn * Dn + (size_t)Qn * Mn;   // 4 scalars
    (void)out_size;

    cudaFuncSetAttribute(gemm_kernel,
                         cudaFuncAttributeMaxDynamicSharedMemorySize, SM_TOT);

    prep0_kernel<<<Mn / 8, 256>>>(x);
    packBc2_kernel<<<(Qn * Kn * 32) / 256, 256>>>(cbs);

    for (int q = 0; q < Qn; q++) {
        gemm_kernel<<<Mn / 128, 128, SM_TOT>>>(q);
        scan_update_kernel<<<Mn / 8, 256>>>(cbs, q, x, out_idx, out_quant,
                                            (q == Qn - 1) ? 1 : 0);
    }

    finalize_kernel<<<1, 256>>>(out_loss);
}

// round 17
// speedup vs baseline: 2.3346x; 2.3346x over previous
#include <cuda_runtime.h>
#include <cuda_bf16.h>
#include <cuda_fp16.h>
#include <cfloat>
#include <cstddef>
#include <cstdint>

// Problem constants (fixed by the reference)
#define Bn 16
#define Tn 2048
#define Dn 256
#define Qn 4
#define Kn 1024
#define Mn (Bn*Tn)          // 32768 tokens

#define LOSS_SLOTS 1024
#define WWIN  4.0f           // candidate window: 2*(bf16 gemm err) + fp16 ulp slack
#define CANDCAP 32

// ------------------------- device global scratch ---------------------------
__device__ __align__(16) float          g_residual[Mn*Dn];
__device__ __align__(16) float          g_c2[Qn*Kn];
__device__ __align__(16) float          g_r2[Mn];
__device__              double          g_losspart[LOSS_SLOTS];
__device__ __align__(16) __nv_bfloat16  g_Apack[(size_t)Mn*Dn];      // bf16(residual)
__device__ __align__(16) __nv_bfloat16  g_Bpack[(size_t)Qn*Kn*Dn];   // bf16(codebooks)
__device__ __align__(16) __half         g_scores[(size_t)Mn*Kn];     // 64 MB approx scores
__device__ __align__(16) float          g_hmin[(size_t)Mn*16];       // per-64-code-half mins

// ------------------------------ PTX helpers --------------------------------
__device__ __forceinline__ uint32_t smem_to_u32(const void* p) {
    uint32_t a;
    asm("{ .reg .u64 t; cvta.to.shared.u64 t, %1; cvt.u32.u64 %0, t; }"
        : "=r"(a) : "l"(p));
    return a;
}
#define CP_ASYNC16(dst, src) \
    asm volatile("cp.async.cg.shared.global [%0], [%1], 16;" :: "r"(dst), "l"(src))
#define CP_COMMIT() asm volatile("cp.async.commit_group;" ::: "memory")
#define CP_WAIT0()  asm volatile("cp.async.wait_group 0;" ::: "memory")
#define LDSM_X4(r0, r1, r2, r3, addr) \
    asm volatile("ldmatrix.sync.aligned.m8n8.x4.shared.b16 {%0,%1,%2,%3}, [%4];" \
                 : "=r"(r0), "=r"(r1), "=r"(r2), "=r"(r3) : "r"(addr))
#define MMA16816(c, a, b0v, b1v) \
    asm volatile("mma.sync.aligned.m16n8k16.row.col.f32.bf16.bf16.f32 " \
                 "{%0,%1,%2,%3}, {%4,%5,%6,%7}, {%8,%9}, {%0,%1,%2,%3};" \
                 : "+f"((c)[0]), "+f"((c)[1]), "+f"((c)[2]), "+f"((c)[3]) \
                 : "r"((a)[0]), "r"((a)[1]), "r"((a)[2]), "r"((a)[3]), \
                   "r"(b0v), "r"(b1v))

// ---------------------------------------------------------------------------
// prep0: residual = x, bf16 pack, r2 (XLA-exact order), zero loss slots.
// ---------------------------------------------------------------------------
__global__ void prep0_kernel(const float* __restrict__ x) {
    int wid = threadIdx.x >> 5, lane = threadIdx.x & 31;
    int token = blockIdx.x * 8 + wid;
    size_t base = (size_t)token * Dn;
    float s = 0.f;
    #pragma unroll
    for (int j = 0; j < 8; j++) {
        int d = lane + 32 * j;
        float v = x[base + d];
        g_residual[base + d] = v;
        g_Apack[base + d] = __float2bfloat16_rn(v);
        s = __fadd_rn(s, __fmul_rn(v, v));
    }
    #pragma unroll
    for (int off = 16; off; off >>= 1)
        s = __fadd_rn(s, __shfl_down_sync(0xffffffffu, s, off));
    if (lane == 0) g_r2[token] = s;
    if (blockIdx.x == 0) {
        for (int i = threadIdx.x; i < LOSS_SLOTS; i += 256) g_losspart[i] = 0.0;
    }
}

// codebooks -> bf16 pack + c2 (XLA-exact order), one warp per codeword
__global__ void packBc2_kernel(const float* __restrict__ cbs) {
    int w    = (blockIdx.x * blockDim.x + threadIdx.x) >> 5;
    int lane = threadIdx.x & 31;
    if (w >= Qn * Kn) return;
    const float* row = cbs + (size_t)w * Dn;
    float s = 0.f;
    #pragma unroll
    for (int j = 0; j < 8; j++) {
        int d = lane + 32 * j;
        float v = row[d];
        g_Bpack[(size_t)w * Dn + d] = __float2bfloat16_rn(v);
        s = __fadd_rn(s, __fmul_rn(v, v));
    }
    #pragma unroll
    for (int off = 16; off; off >>= 1)
        s = __fadd_rn(s, __shfl_down_sync(0xffffffffu, s, off));
    if (lane == 0) g_c2[w] = s;
}

// ---------------------------------------------------------------------------
// bf16 HMMA GEMM: 128 tokens/CTA x 1024 codes, K=256. A resident in SMEM,
// B double-buffered. 128 threads (4 warps, 2x2), warp tile 64x64, register
// double-buffered fragments (round-15 mainloop, unchanged numerics).
// Epilogue: fp16 scores + per-(row, 64-code-half) fp32 min.
// ---------------------------------------------------------------------------
#define SM_A  0                      // 4 chunks x 16384 = 65536
#define SM_B0 65536
#define SM_B1 (65536 + 16384)
#define SM_C2 (65536 + 32768)
#define SM_TOT (65536 + 32768 + 4096)

__global__ void __launch_bounds__(128, 2)
gemm_kernel(int q)
{
    extern __shared__ char smem[];
    uint32_t sb = smem_to_u32(smem);
    float* c2s = (float*)(smem + SM_C2);

    int tid = threadIdx.x, lane = tid & 31, wid = tid >> 5;
    int wm = wid >> 1, wn = wid & 1;           // 2 x 2 warp grid, tile 64x64
    int rowBase = blockIdx.x * 128;

    for (int i = tid; i < Kn; i += 128) c2s[i] = g_c2[q * Kn + i];

    float r2a[4][2];
    #pragma unroll
    for (int mf = 0; mf < 4; mf++)
        #pragma unroll
        for (int h = 0; h < 2; h++)
            r2a[mf][h] = g_r2[rowBase + wm * 64 + mf * 16 + (lane >> 2) + h * 8];

    const __nv_bfloat16* baseB = g_Bpack + (size_t)q * Kn * Dn;

    // A -> SMEM once: chunked layout [cc][row][64k]; 32 x 16B per thread
    #pragma unroll
    for (int j = 0; j < 32; j++) {
        int linear = tid + 128 * j;             // 0..4095
        int row = linear >> 5;                  // 0..127
        int m8  = linear & 31;
        int cc  = m8 >> 3, m8c = m8 & 7;
        uint32_t sw = (uint32_t)((m8c ^ (row & 7)) << 4);
        CP_ASYNC16(sb + SM_A + cc * 16384 + row * 128 + sw,
                   g_Apack + (size_t)(rowBase + row) * Dn + m8 * 8);
    }
    CP_COMMIT();

    // B chunk 0: 8 x 16B per thread
    #pragma unroll
    for (int j = 0; j < 8; j++) {
        int linear = tid + 128 * j;             // 0..1023
        int row = linear >> 3, m8 = linear & 7;
        uint32_t sw = (uint32_t)((m8 ^ (row & 7)) << 4);
        CP_ASYNC16(sb + SM_B0 + row * 128 + sw,
                   baseB + (size_t)row * Dn + m8 * 8);
    }
    CP_COMMIT();

    float acc[4][8][4];
    #pragma unroll
    for (int a = 0; a < 4; a++)
        #pragma unroll
        for (int b = 0; b < 8; b++)
            #pragma unroll
            for (int c = 0; c < 4; c++) acc[a][b][c] = 0.f;

    const int tq = lane >> 3;                   // ldmatrix quad selector

    for (int bc = 0; bc < 32; bc++) {
        int nt = bc >> 2, cc = bc & 3;
        CP_WAIT0();
        __syncthreads();

        if (bc < 31) {
            int nbc = bc + 1;
            int nnt = nbc >> 2, ncc = nbc & 3;
            uint32_t buf = (nbc & 1) ? SM_B1 : SM_B0;
            int koff = ncc * 64;
            #pragma unroll
            for (int j = 0; j < 8; j++) {
                int linear = tid + 128 * j;
                int row = linear >> 3, m8 = linear & 7;
                uint32_t sw = (uint32_t)((m8 ^ (row & 7)) << 4);
                CP_ASYNC16(sb + buf + row * 128 + sw,
                           baseB + (size_t)(nnt * 128 + row) * Dn + koff + m8 * 8);
            }
            CP_COMMIT();
        }

        uint32_t abase = sb + SM_A + cc * 16384;
        uint32_t bbase = sb + ((bc & 1) ? SM_B1 : SM_B0);

        // double-buffered fragments: [buf][frag][4 regs]
        uint32_t afr[2][4][4], bfr[2][4][4];

        // load ks=0 into buffer 0
        #pragma unroll
        for (int mf = 0; mf < 4; mf++) {
            int row = wm * 64 + mf * 16 + (lane & 7) + ((tq & 1) << 3);
            int kk  = (tq >> 1) << 3;
            uint32_t addr = abase + row * 128 + ((((kk >> 3) ^ (row & 7)) << 4));
            LDSM_X4(afr[0][mf][0], afr[0][mf][1], afr[0][mf][2], afr[0][mf][3], addr);
        }
        #pragma unroll
        for (int nf2 = 0; nf2 < 4; nf2++) {
            int row = wn * 64 + nf2 * 16 + ((tq >> 1) << 3) + (lane & 7);
            int kk  = (tq & 1) << 3;
            uint32_t addr = bbase + row * 128 + ((((kk >> 3) ^ (row & 7)) << 4));
            LDSM_X4(bfr[0][nf2][0], bfr[0][nf2][1], bfr[0][nf2][2], bfr[0][nf2][3], addr);
        }

        #pragma unroll
        for (int ks = 0; ks < 4; ks++) {
            int cur = ks & 1, nxt = cur ^ 1;
            if (ks < 3) {
                // prefetch ks+1 fragments while MMAs of ks execute
                #pragma unroll
                for (int mf = 0; mf < 4; mf++) {
                    int row = wm * 64 + mf * 16 + (lane & 7) + ((tq & 1) << 3);
                    int kk  = (ks + 1) * 16 + ((tq >> 1) << 3);
                    uint32_t addr = abase + row * 128 + ((((kk >> 3) ^ (row & 7)) << 4));
                    LDSM_X4(afr[nxt][mf][0], afr[nxt][mf][1], afr[nxt][mf][2], afr[nxt][mf][3], addr);
                }
                #pragma unroll
                for (int nf2 = 0; nf2 < 4; nf2++) {
                    int row = wn * 64 + nf2 * 16 + ((tq >> 1) << 3) + (lane & 7);
                    int kk  = (ks + 1) * 16 + ((tq & 1) << 3);
                    uint32_t addr = bbase + row * 128 + ((((kk >> 3) ^ (row & 7)) << 4));
                    LDSM_X4(bfr[nxt][nf2][0], bfr[nxt][nf2][1], bfr[nxt][nf2][2], bfr[nxt][nf2][3], addr);
                }
            }
            #pragma unroll
            for (int nf2 = 0; nf2 < 4; nf2++) {
                #pragma unroll
                for (int mf = 0; mf < 4; mf++) {
                    MMA16816(acc[mf][nf2 * 2],     afr[cur][mf], bfr[cur][nf2][0], bfr[cur][nf2][1]);
                    MMA16816(acc[mf][nf2 * 2 + 1], afr[cur][mf], bfr[cur][nf2][2], bfr[cur][nf2][3]);
                }
            }
        }

        if (cc == 3) {
            // ---- epilogue tile nt: fp16 scores + half-tile mins ----
            #pragma unroll
            for (int mf = 0; mf < 4; mf++) {
                int ra = rowBase + wm * 64 + mf * 16 + (lane >> 2);
                float lmin0 = FLT_MAX, lmin1 = FLT_MAX;
                #pragma unroll
                for (int nf = 0; nf < 8; nf++) {
                    int col = nt * 128 + wn * 64 + nf * 8 + (lane & 3) * 2;
                    float cA = c2s[col], cB = c2s[col + 1];
                    float s0x = __fadd_rn(__fsub_rn(r2a[mf][0], __fmul_rn(2.f, acc[mf][nf][0])), cA);
                    float s0y = __fadd_rn(__fsub_rn(r2a[mf][0], __fmul_rn(2.f, acc[mf][nf][1])), cB);
                    float s1x = __fadd_rn(__fsub_rn(r2a[mf][1], __fmul_rn(2.f, acc[mf][nf][2])), cA);
                    float s1y = __fadd_rn(__fsub_rn(r2a[mf][1], __fmul_rn(2.f, acc[mf][nf][3])), cB);
                    lmin0 = fminf(lmin0, fminf(s0x, s0y));
                    lmin1 = fminf(lmin1, fminf(s1x, s1y));
                    *(__half2*)(g_scores + (size_t)ra * Kn + col)       = __floats2half2_rn(s0x, s0y);
                    *(__half2*)(g_scores + (size_t)(ra + 8) * Kn + col) = __floats2half2_rn(s1x, s1y);
                }
                // quad-reduce (lanes sharing a row) and store half-tile mins
                lmin0 = fminf(lmin0, __shfl_xor_sync(0xffffffffu, lmin0, 1));
                lmin0 = fminf(lmin0, __shfl_xor_sync(0xffffffffu, lmin0, 2));
                lmin1 = fminf(lmin1, __shfl_xor_sync(0xffffffffu, lmin1, 1));
                lmin1 = fminf(lmin1, __shfl_xor_sync(0xffffffffu, lmin1, 2));
                if ((lane & 3) == 0) {
                    g_hmin[(size_t)ra * 16 + nt * 2 + wn]       = lmin0;
                    g_hmin[(size_t)(ra + 8) * 16 + nt * 2 + wn] = lmin1;
                }
            }
            #pragma unroll
            for (int a = 0; a < 4; a++)
                #pragma unroll
                for (int b = 0; b < 8; b++)
                    #pragma unroll
                    for (int c = 0; c < 4; c++) acc[a][b][c] = 0.f;
        }
    }
}

// ---------------------------------------------------------------------------
// Fused scan + update with half-tile pruning. One warp per token.
// Ballot + bit-scan over surviving half-tiles (same candidate semantics as
// the round-15 prune loop, ~14 fewer iterations). Candidates within WWIN
// exact-rechecked (round-3 bit-exact chain). Residual preloaded.
// ---------------------------------------------------------------------------
__global__ void scan_update_kernel(const float* __restrict__ cbs, int q,
                                   const float* __restrict__ x,
                                   float* __restrict__ out_idx_f,
                                   float* __restrict__ out_quant, int is_last)
{
    int wid = threadIdx.x >> 5, lane = threadIdx.x & 31;
    int token = blockIdx.x * 8 + wid;
    const float* cb = cbs + (size_t)q * Kn * Dn;
    size_t base = (size_t)token * Dn;

    // preload my 8 residual values (independent of winner; overlaps scan)
    float rres[8];
    #pragma unroll
    for (int j = 0; j < 8; j++) rres[j] = g_residual[base + lane + 32 * j];

    // half-tile mins (fp32, exact mins of pre-rounding scores)
    float hm = (lane < 16) ? g_hmin[(size_t)token * 16 + lane] : FLT_MAX;
    float mn = hm;
    #pragma unroll
    for (int off = 16; off; off >>= 1)
        mn = fminf(mn, __shfl_xor_sync(0xffffffffu, mn, off));
    float thr  = mn + WWIN;
    float thrt = thr + 0.5f;        // fp16-ulp guard for pruning

    __shared__ int cnts[8];
    __shared__ int lists[8][CANDCAP];
    if (lane == 0) cnts[wid] = 0;
    __syncwarp();

    // ballot over surviving half-tiles; iterate only set bits
    uint32_t survive = __ballot_sync(0xffffffffu, lane < 16 && hm <= thrt);
    const uint32_t* sp = (const uint32_t*)(g_scores + (size_t)token * Kn);
    while (survive) {
        int ht = __ffs(survive) - 1;
        survive &= survive - 1;
        uint32_t u = sp[ht * 32 + lane];
        float2 f = __half22float2(*(__half2*)&u);
        if (f.x <= thr) {
            int p = atomicAdd(&cnts[wid], 1);
            if (p < CANDCAP) lists[wid][p] = ht * 64 + lane * 2;
        }
        if (f.y <= thr) {
            int p = atomicAdd(&cnts[wid], 1);
            if (p < CANDCAP) lists[wid][p] = ht * 64 + lane * 2 + 1;
        }
    }
    __syncwarp();
    int cnt = cnts[wid];
    int winner;

    if (cnt == 1) {
        winner = lists[wid][0];
    } else {
        const float* rrow = g_residual + base;
        float r2 = g_r2[token];
        float bv = FLT_MAX; int bi = 0x7fffffff;
        if (cnt <= CANDCAP) {
            if (lane < cnt) {
                int k = lists[wid][lane];
                const float* cr = cb + (size_t)k * Dn;
                float acc = 0.f;
                #pragma unroll 8
                for (int d = 0; d < Dn; d++) acc = __fmaf_rn(rrow[d], cr[d], acc);
                bv = __fadd_rn(__fsub_rn(r2, __fmul_rn(2.f, acc)), g_c2[q * Kn + k]);
                bi = k;
            }
        } else {
            for (int k = lane; k < Kn; k += 32) {
                const float* cr = cb + (size_t)k * Dn;
                float acc = 0.f;
                #pragma unroll 8
                for (int d = 0; d < Dn; d++) acc = __fmaf_rn(rrow[d], cr[d], acc);
                float s = __fadd_rn(__fsub_rn(r2, __fmul_rn(2.f, acc)), g_c2[q * Kn + k]);
                if (s < bv || (s == bv && k < bi)) { bv = s; bi = k; }
            }
        }
        #pragma unroll
        for (int off = 16; off; off >>= 1) {
            float ov = __shfl_xor_sync(0xffffffffu, bv, off);
            int   oi = __shfl_xor_sync(0xffffffffu, bi, off);
            if (ov < bv || (ov == bv && oi < bi)) { bv = ov; bi = oi; }
        }
        winner = bi;
    }

    // ---- update (bit-exact residual chain; r2 in XLA-exact order) ----
    const float* cbrow = cb + (size_t)winner * Dn;
    float s = 0.f;
    #pragma unroll
    for (int j = 0; j < 8; j++) {
        int d = lane + 32 * j;
        float qv = cbrow[d];
        float r  = __fsub_rn(rres[j], qv);
        if (!is_last) {
            g_residual[base + d] = r;
            g_Apack[base + d] = __float2bfloat16_rn(r);
        } else {
            out_quant[base + d] = __fsub_rn(x[base + d], r);
        }
        s = __fadd_rn(s, __fmul_rn(r, r));
    }
    #pragma unroll
    for (int off = 16; off; off >>= 1)
        s = __fadd_rn(s, __shfl_down_sync(0xffffffffu, s, off));
    if (lane == 0) {
        if (!is_last) g_r2[token] = s;
        atomicAdd(&g_losspart[token & (LOSS_SLOTS - 1)], (double)s);
        out_idx_f[(size_t)q * Mn + token] = (float)winner;
    }
}

__global__ void finalize_kernel(float* __restrict__ out_loss)
{
    __shared__ double red[256];
    double s = 0.0;
    for (int i = threadIdx.x; i < LOSS_SLOTS; i += 256) s += g_losspart[i];
    red[threadIdx.x] = s;
    __syncthreads();
    #pragma unroll
    for (int st = 128; st > 0; st >>= 1) {
        if (threadIdx.x < st) red[threadIdx.x] += red[threadIdx.x + st];
        __syncthreads();
    }
    if (threadIdx.x == 0) {
        float v = (float)(1.25 * red[0] / (double)((size_t)Mn * Dn));
        #pragma unroll
        for (int q = 0; q < Qn; q++) out_loss[q] = v;
    }
}

// ---------------------------------------------------------------------------
extern "C" void kernel_launch(void* const* d_in, const int* in_sizes, int n_in,
                              void* d_out, int out_size)
{
    const float* x   = (const float*)d_in[0];
    const float* cbs = (const float*)d_in[1];
    if (n_in >= 2 && in_sizes[0] == Qn * Kn * Dn && in_sizes[1] == Mn * Dn) {
        const float* t = x; x = cbs; cbs = t;
    }

    float* out       = (float*)d_out;
    float* out_quant = out;                                       // [B,T,D]
    float* out_idx   = out + (size_t)Mn * Dn;                     // [Q,B,T]
    float* out_loss  = out + (size_t)Mn * Dn + (size_t)Qn * Mn;   // 4 scalars
    (void)out_size;

    cudaFuncSetAttribute(gemm_kernel,
                         cudaFuncAttributeMaxDynamicSharedMemorySize, SM_TOT);

    prep0_kernel<<<Mn / 8, 256>>>(x);
    packBc2_kernel<<<(Qn * Kn * 32) / 256, 256>>>(cbs);

    for (int q = 0; q < Qn; q++) {
        gemm_kernel<<<Mn / 128, 128, SM_TOT>>>(q);
        scan_update_kernel<<<Mn / 8, 256>>>(cbs, q, x, out_idx, out_quant,
                                            (q == Qn - 1) ? 1 : 0);
    }

    finalize_kernel<<<1, 256>>>(out_loss);
}